// round 6
// baseline (speedup 1.0000x reference)
#include <cuda_runtime.h>

// ---------------------------------------------------------------------------
// SparseNeuralNetwork: 256 independent 1->16->8->1 micro-MLPs.
//   out[b,o] = b2[o] + sum_i MLP_{i,o}(x[b,i])
//
// f32x2 packed over SAMPLE PAIRS (weights pre-duplicated), k-outer
// accumulation. This round: __launch_bounds__(256,4) -> 4 blocks/SM ->
// single wave at grid=512 (capacity 592), 8 warps/SMSP.
// ---------------------------------------------------------------------------

typedef unsigned long long ull;

// Duplicated compact weights (each scalar stored twice for f32x2 operands).
__device__ float g_w0d[8192];    // [io(256)][k(16)][2]
__device__ float g_b0d[8192];    // [io][k][2]
__device__ float g_w1d[65536];   // [io][k(16)][j(8)][2]
__device__ float g_b1d[4096];    // [io][j(8)][2]
__device__ float g_w2d[4096];    // [io][j(8)][2]

__global__ void gather_kernel(const float* __restrict__ W0,
                              const float* __restrict__ b0,
                              const float* __restrict__ W1,
                              const float* __restrict__ b1,
                              const float* __restrict__ W2,
                              const float* __restrict__ b2,
                              float* __restrict__ out,
                              int out_elems) {
    int t = blockIdx.x * blockDim.x + threadIdx.x;
    if (t < out_elems) out[t] = b2[t & 15];          // preset out = b2[o]
    if (t < 65536) {                                  // w1 dup: [io][k][j][2]
        int j  = (t >> 1) & 7;
        int k  = (t >> 4) & 15;
        int io = t >> 8;
        int r  = io * 8 + j;
        g_w1d[t] = W1[r * 4096 + io * 16 + k];
    }
    if (t < 8192) {                                   // w0/b0 dup: [io][k][2]
        int k  = (t >> 1) & 15;
        int io = t >> 5;
        int r  = io * 16 + k;
        int i  = io >> 4;
        g_w0d[t] = W0[r * 16 + i];
        g_b0d[t] = b0[r];
    }
    if (t < 4096) {                                   // b1/w2 dup: [io][j][2]
        int j  = (t >> 1) & 7;
        int io = t >> 4;
        int r  = io * 8 + j;
        g_b1d[t] = b1[r];
        g_w2d[t] = W2[(io & 15) * 2048 + r];
    }
}

// ---- packed f32x2 helpers --------------------------------------------------
__device__ __forceinline__ void up2(ull v, float& lo, float& hi) {
    asm("mov.b64 {%0, %1}, %2;" : "=f"(lo), "=f"(hi) : "l"(v));
}
__device__ __forceinline__ ull fma2(ull a, ull b, ull c) {
    ull d;
    asm("fma.rn.f32x2 %0, %1, %2, %3;" : "=l"(d) : "l"(a), "l"(b), "l"(c));
    return d;
}
// packed relu: unpack, 2x FMNMX, repack (no packed max in PTX f32x2 family)
__device__ __forceinline__ ull relu2(ull v) {
    float a, b;
    up2(v, a, b);
    a = fmaxf(a, 0.0f);
    b = fmaxf(b, 0.0f);
    ull d;
    asm("mov.b64 %0, {%1, %2};" : "=l"(d) : "f"(a), "f"(b));
    return d;
}

// ---------------------------------------------------------------------------
// mlp kernel: blockIdx.x encodes (chunk, i-quarter, o-half):
//   oh = b & 1, iq = (b>>1) & 3, chunk = b >> 3
// block = 256 threads = 8 warps; warp -> output o = oh*8 + warp;
// lane handles 4 samples (2 f32x2 packs), chunk = 128 samples.
// ---------------------------------------------------------------------------
__global__ __launch_bounds__(256, 4)
void mlp_kernel(const float* __restrict__ x,
                float* __restrict__ out,
                int n) {
    __shared__ float sw1d[8192];   // [ii(4)][oo(8)][k(16)][j(8)][2]
    __shared__ float sw0d[1024];   // [ii][oo][k][2]
    __shared__ float sb0d[1024];
    __shared__ float sb1d[512];    // [ii][oo][j][2]
    __shared__ float sw2d[512];
    __shared__ float sx[512];      // [ii][128 samples]

    const int tid  = threadIdx.x;
    const int w    = tid >> 5;
    const int lane = tid & 31;

    const int bidx  = blockIdx.x;
    const int oh    = bidx & 1;
    const int iq    = (bidx >> 1) & 3;
    const int chunk = bidx >> 3;
    const int base  = chunk * 128;

    // ---- stage duplicated weight slices (contiguous per ii) ---------------
    #pragma unroll
    for (int ii = 0; ii < 4; ++ii) {
        const int i   = iq * 4 + ii;
        const int gio = i * 16 + oh * 8;   // first (i,o) of this block's slice
        {
            const float4* s = (const float4*)(g_w1d + gio * 256);
            float4* d = (float4*)(sw1d + ii * 2048);
            for (int t = tid; t < 512; t += 256) d[t] = s[t];
        }
        if (tid < 64) {
            ((float4*)(sw0d + ii * 256))[tid] = ((const float4*)(g_w0d + gio * 32))[tid];
            ((float4*)(sb0d + ii * 256))[tid] = ((const float4*)(g_b0d + gio * 32))[tid];
        }
        if (tid < 32) {
            ((float4*)(sb1d + ii * 128))[tid] = ((const float4*)(g_b1d + gio * 16))[tid];
            ((float4*)(sw2d + ii * 128))[tid] = ((const float4*)(g_w2d + gio * 16))[tid];
        }
    }
    // x transposed: sx[ii][s] = x[(base+s)*16 + (iq*4+ii)]
    for (int e = tid; e < 512; e += 256) {
        int ii = e >> 7, s = e & 127;
        int gs = base + s;
        sx[ii * 128 + s] = (gs < n) ? x[gs * 16 + (iq * 4 + ii)] : 0.0f;
    }
    __syncthreads();

    ull outp0 = 0, outp1 = 0;   // packed outputs: (s0,s1) and (s2,s3)

    #pragma unroll 1
    for (int ii = 0; ii < 4; ++ii) {
        const int bio = ii * 8 + w;   // local (ii, oo) slot

        // x packs: 4 consecutive samples -> (s0,s1), (s2,s3)
        const ulonglong2 xp = *(const ulonglong2*)(sx + ii * 128 + 4 * lane);

        // accumulators init = b1 (duplicated), one set per sample pack
        ull acc0[8], acc1[8];
        {
            const ulonglong2* bp = (const ulonglong2*)(sb1d + bio * 16);
            #pragma unroll
            for (int q = 0; q < 4; ++q) {
                ulonglong2 v = bp[q];
                acc0[2 * q] = v.x; acc0[2 * q + 1] = v.y;
                acc1[2 * q] = v.x; acc1[2 * q + 1] = v.y;
            }
        }

        const float* w0base = sw0d + bio * 32;
        const float* b0base = sb0d + bio * 32;
        const float* w1base = sw1d + bio * 256;

        #pragma unroll
        for (int k2 = 0; k2 < 8; ++k2) {
            // layer 0 for k = 2*k2 and 2*k2+1 (dup weights, packed samples)
            const ulonglong2 w0p = *(const ulonglong2*)(w0base + k2 * 4);
            const ulonglong2 b0p = *(const ulonglong2*)(b0base + k2 * 4);
            const ull y00 = relu2(fma2(w0p.x, xp.x, b0p.x));  // k,   pack01
            const ull y01 = relu2(fma2(w0p.x, xp.y, b0p.x));  // k,   pack23
            const ull y10 = relu2(fma2(w0p.y, xp.x, b0p.y));  // k+1, pack01
            const ull y11 = relu2(fma2(w0p.y, xp.y, b0p.y));  // k+1, pack23

            // layer 1 scatter: k row (8 dup weights over j)
            {
                const ulonglong2* w1p = (const ulonglong2*)(w1base + (2 * k2) * 16);
                #pragma unroll
                for (int q = 0; q < 4; ++q) {
                    ulonglong2 v = w1p[q];
                    acc0[2 * q]     = fma2(v.x, y00, acc0[2 * q]);
                    acc1[2 * q]     = fma2(v.x, y01, acc1[2 * q]);
                    acc0[2 * q + 1] = fma2(v.y, y00, acc0[2 * q + 1]);
                    acc1[2 * q + 1] = fma2(v.y, y01, acc1[2 * q + 1]);
                }
            }
            // k+1 row
            {
                const ulonglong2* w1p = (const ulonglong2*)(w1base + (2 * k2 + 1) * 16);
                #pragma unroll
                for (int q = 0; q < 4; ++q) {
                    ulonglong2 v = w1p[q];
                    acc0[2 * q]     = fma2(v.x, y10, acc0[2 * q]);
                    acc1[2 * q]     = fma2(v.x, y11, acc1[2 * q]);
                    acc0[2 * q + 1] = fma2(v.y, y10, acc0[2 * q + 1]);
                    acc1[2 * q + 1] = fma2(v.y, y11, acc1[2 * q + 1]);
                }
            }
        }

        // relu + layer-2 fold (still packed over samples; no horizontal!)
        {
            const ulonglong2* w2p = (const ulonglong2*)(sw2d + bio * 16);
            #pragma unroll
            for (int q = 0; q < 4; ++q) {
                ulonglong2 v = w2p[q];
                outp0 = fma2(v.x, relu2(acc0[2 * q]), outp0);
                outp1 = fma2(v.x, relu2(acc1[2 * q]), outp1);
                outp0 = fma2(v.y, relu2(acc0[2 * q + 1]), outp0);
                outp1 = fma2(v.y, relu2(acc1[2 * q + 1]), outp1);
            }
        }
    }

    // ---- combine i-quarter partials via atomics ----------------------------
    float v0, v1, v2, v3;
    up2(outp0, v0, v1);
    up2(outp1, v2, v3);
    const int o  = oh * 8 + w;
    const int s0 = base + 4 * lane;
    if (s0 + 0 < n) atomicAdd(out + (s0 + 0) * 16 + o, v0);
    if (s0 + 1 < n) atomicAdd(out + (s0 + 1) * 16 + o, v1);
    if (s0 + 2 < n) atomicAdd(out + (s0 + 2) * 16 + o, v2);
    if (s0 + 3 < n) atomicAdd(out + (s0 + 3) * 16 + o, v3);
}

extern "C" void kernel_launch(void* const* d_in, const int* in_sizes, int n_in,
                              void* d_out, int out_size) {
    const float *x = nullptr, *W0 = nullptr, *b0 = nullptr, *W1 = nullptr;
    const float *b1 = nullptr, *W2 = nullptr, *b2 = nullptr;
    for (int idx = 0; idx < n_in; ++idx) {
        switch (in_sizes[idx]) {
            case 131072:  x  = (const float*)d_in[idx]; break;   // [8192,16]
            case 65536:   W0 = (const float*)d_in[idx]; break;   // [4096,16]
            case 4096:    b0 = (const float*)d_in[idx]; break;
            case 8388608: W1 = (const float*)d_in[idx]; break;   // [2048,4096]
            case 2048:    b1 = (const float*)d_in[idx]; break;
            case 32768:   W2 = (const float*)d_in[idx]; break;   // [16,2048]
            case 16:      b2 = (const float*)d_in[idx]; break;
            default: break;
        }
    }

    const int n = out_size / 16;

    // gather/dup weights + preset out = b2  (needs >= 131072 threads)
    gather_kernel<<<512, 256>>>(W0, b0, W1, b1, W2, b2, (float*)d_out, out_size);

    const int chunks = (n + 127) / 128;
    mlp_kernel<<<chunks * 8, 256>>>(x, (float*)d_out, n);
}

// round 9
// speedup vs baseline: 1.0755x; 1.0755x over previous
#include <cuda_runtime.h>

// ---------------------------------------------------------------------------
// SparseNeuralNetwork: 256 independent 1->16->8->1 micro-MLPs.
//   out[b,o] = b2[o] + sum_i MLP_{i,o}(x[b,i])
//
// f32x2 packed over SAMPLE PAIRS (weights pre-duplicated in smem), k-outer
// accumulation. R7: 8 samples/thread (4 packs) -> weight LDS per sample
// halved, 32 independent acc chains; 128-reg budget (2 blocks/SM) so ptxas
// can pipeline LDS deeply. grid=256, single wave.
// ---------------------------------------------------------------------------

typedef unsigned long long ull;

// Duplicated compact weights (each scalar stored twice for f32x2 operands).
__device__ float g_w0d[8192];    // [io(256)][k(16)][2]
__device__ float g_b0d[8192];    // [io][k][2]
__device__ float g_w1d[65536];   // [io][k(16)][j(8)][2]
__device__ float g_b1d[4096];    // [io][j(8)][2]
__device__ float g_w2d[4096];    // [io][j(8)][2]

__global__ void gather_kernel(const float* __restrict__ W0,
                              const float* __restrict__ b0,
                              const float* __restrict__ W1,
                              const float* __restrict__ b1,
                              const float* __restrict__ W2,
                              const float* __restrict__ b2,
                              float* __restrict__ out,
                              int out_elems) {
    int t = blockIdx.x * blockDim.x + threadIdx.x;
    if (t < out_elems) out[t] = b2[t & 15];          // preset out = b2[o]
    if (t < 65536) {                                  // w1 dup: [io][k][j][2]
        int j  = (t >> 1) & 7;
        int k  = (t >> 4) & 15;
        int io = t >> 8;
        int r  = io * 8 + j;
        g_w1d[t] = W1[r * 4096 + io * 16 + k];
    }
    if (t < 8192) {                                   // w0/b0 dup: [io][k][2]
        int k  = (t >> 1) & 15;
        int io = t >> 5;
        int r  = io * 16 + k;
        int i  = io >> 4;
        g_w0d[t] = W0[r * 16 + i];
        g_b0d[t] = b0[r];
    }
    if (t < 4096) {                                   // b1/w2 dup: [io][j][2]
        int j  = (t >> 1) & 7;
        int io = t >> 4;
        int r  = io * 8 + j;
        g_b1d[t] = b1[r];
        g_w2d[t] = W2[(io & 15) * 2048 + r];
    }
}

// ---- packed f32x2 helpers --------------------------------------------------
__device__ __forceinline__ void up2(ull v, float& lo, float& hi) {
    asm("mov.b64 {%0, %1}, %2;" : "=f"(lo), "=f"(hi) : "l"(v));
}
__device__ __forceinline__ ull fma2(ull a, ull b, ull c) {
    ull d;
    asm("fma.rn.f32x2 %0, %1, %2, %3;" : "=l"(d) : "l"(a), "l"(b), "l"(c));
    return d;
}
// packed relu: unpack, 2x FMNMX (alu pipe), repack (movs usually coalesced)
__device__ __forceinline__ ull relu2(ull v) {
    float a, b;
    up2(v, a, b);
    a = fmaxf(a, 0.0f);
    b = fmaxf(b, 0.0f);
    ull d;
    asm("mov.b64 %0, {%1, %2};" : "=l"(d) : "f"(a), "f"(b));
    return d;
}

// ---------------------------------------------------------------------------
// mlp kernel: blockIdx.x encodes (chunk, i-quarter, o-half):
//   oh = b & 1, iq = (b>>1) & 3, chunk = b >> 3
// block = 256 threads = 8 warps; warp -> output o = oh*8 + warp;
// lane handles 8 samples (4 f32x2 packs), chunk = 256 samples.
// ---------------------------------------------------------------------------
#define NPACK 4   // sample pairs per thread

__global__ __launch_bounds__(256, 2)
void mlp_kernel(const float* __restrict__ x,
                float* __restrict__ out,
                int n) {
    __shared__ float sw1d[8192];   // [ii(4)][oo(8)][k(16)][j(8)][2]
    __shared__ float sw0d[1024];   // [ii][oo][k][2]
    __shared__ float sb0d[1024];
    __shared__ float sb1d[512];    // [ii][oo][j][2]
    __shared__ float sw2d[512];
    __shared__ float sx[1024];     // [ii][256 samples]

    const int tid  = threadIdx.x;
    const int w    = tid >> 5;
    const int lane = tid & 31;

    const int bidx  = blockIdx.x;
    const int oh    = bidx & 1;
    const int iq    = (bidx >> 1) & 3;
    const int chunk = bidx >> 3;
    const int base  = chunk * 256;

    // ---- stage duplicated weight slices (contiguous per ii) ---------------
    #pragma unroll
    for (int ii = 0; ii < 4; ++ii) {
        const int i   = iq * 4 + ii;
        const int gio = i * 16 + oh * 8;   // first (i,o) of this block's slice
        {
            const float4* s = (const float4*)(g_w1d + gio * 256);
            float4* d = (float4*)(sw1d + ii * 2048);
            for (int t = tid; t < 512; t += 256) d[t] = s[t];
        }
        if (tid < 64) {
            ((float4*)(sw0d + ii * 256))[tid] = ((const float4*)(g_w0d + gio * 32))[tid];
            ((float4*)(sb0d + ii * 256))[tid] = ((const float4*)(g_b0d + gio * 32))[tid];
        }
        if (tid < 32) {
            ((float4*)(sb1d + ii * 128))[tid] = ((const float4*)(g_b1d + gio * 16))[tid];
            ((float4*)(sw2d + ii * 128))[tid] = ((const float4*)(g_w2d + gio * 16))[tid];
        }
    }
    // x transposed: sx[ii][s] = x[(base+s)*16 + (iq*4+ii)]
    for (int e = tid; e < 1024; e += 256) {
        int ii = e >> 8, s = e & 255;
        int gs = base + s;
        sx[ii * 256 + s] = (gs < n) ? x[gs * 16 + (iq * 4 + ii)] : 0.0f;
    }
    __syncthreads();

    ull outp[NPACK];                 // packed outputs per sample pair
    #pragma unroll
    for (int p = 0; p < NPACK; ++p) outp[p] = 0;

    #pragma unroll 1
    for (int ii = 0; ii < 4; ++ii) {
        const int bio = ii * 8 + w;   // local (ii, oo) slot

        // x packs: 8 consecutive samples -> 4 packs (two LDS.128)
        ull xp[NPACK];
        {
            const ulonglong2 a = *(const ulonglong2*)(sx + ii * 256 + 8 * lane);
            const ulonglong2 b = *(const ulonglong2*)(sx + ii * 256 + 8 * lane + 4);
            xp[0] = a.x; xp[1] = a.y; xp[2] = b.x; xp[3] = b.y;
        }

        // accumulators init = b1 (duplicated), one set of 8 per pack
        ull acc[NPACK][8];
        {
            const ulonglong2* bp = (const ulonglong2*)(sb1d + bio * 16);
            #pragma unroll
            for (int q = 0; q < 4; ++q) {
                ulonglong2 v = bp[q];
                #pragma unroll
                for (int p = 0; p < NPACK; ++p) {
                    acc[p][2 * q]     = v.x;
                    acc[p][2 * q + 1] = v.y;
                }
            }
        }

        const float* w0base = sw0d + bio * 32;
        const float* b0base = sb0d + bio * 32;
        const float* w1base = sw1d + bio * 256;

        #pragma unroll
        for (int k2 = 0; k2 < 8; ++k2) {
            // layer 0 for k = 2*k2 and 2*k2+1 (dup weights, packed samples)
            const ulonglong2 w0p = *(const ulonglong2*)(w0base + k2 * 4);
            const ulonglong2 b0p = *(const ulonglong2*)(b0base + k2 * 4);
            ull ya[NPACK], yb[NPACK];
            #pragma unroll
            for (int p = 0; p < NPACK; ++p) {
                ya[p] = relu2(fma2(w0p.x, xp[p], b0p.x));   // unit k
                yb[p] = relu2(fma2(w0p.y, xp[p], b0p.y));   // unit k+1
            }

            // layer 1 scatter: k row then k+1 row (8 dup weights over j)
            {
                const ulonglong2* w1p = (const ulonglong2*)(w1base + (2 * k2) * 16);
                #pragma unroll
                for (int q = 0; q < 4; ++q) {
                    ulonglong2 v = w1p[q];
                    #pragma unroll
                    for (int p = 0; p < NPACK; ++p) {
                        acc[p][2 * q]     = fma2(v.x, ya[p], acc[p][2 * q]);
                        acc[p][2 * q + 1] = fma2(v.y, ya[p], acc[p][2 * q + 1]);
                    }
                }
            }
            {
                const ulonglong2* w1p = (const ulonglong2*)(w1base + (2 * k2 + 1) * 16);
                #pragma unroll
                for (int q = 0; q < 4; ++q) {
                    ulonglong2 v = w1p[q];
                    #pragma unroll
                    for (int p = 0; p < NPACK; ++p) {
                        acc[p][2 * q]     = fma2(v.x, yb[p], acc[p][2 * q]);
                        acc[p][2 * q + 1] = fma2(v.y, yb[p], acc[p][2 * q + 1]);
                    }
                }
            }
        }

        // relu + layer-2 fold (still packed over samples)
        {
            const ulonglong2* w2p = (const ulonglong2*)(sw2d + bio * 16);
            #pragma unroll
            for (int q = 0; q < 4; ++q) {
                ulonglong2 v = w2p[q];
                #pragma unroll
                for (int p = 0; p < NPACK; ++p) {
                    outp[p] = fma2(v.x, relu2(acc[p][2 * q]), outp[p]);
                    outp[p] = fma2(v.y, relu2(acc[p][2 * q + 1]), outp[p]);
                }
            }
        }
    }

    // ---- combine i-quarter partials via atomics ----------------------------
    const int o  = oh * 8 + w;
    const int s0 = base + 8 * lane;
    #pragma unroll
    for (int p = 0; p < NPACK; ++p) {
        float v0, v1;
        up2(outp[p], v0, v1);
        int s = s0 + 2 * p;
        if (s + 0 < n) atomicAdd(out + (s + 0) * 16 + o, v0);
        if (s + 1 < n) atomicAdd(out + (s + 1) * 16 + o, v1);
    }
}

extern "C" void kernel_launch(void* const* d_in, const int* in_sizes, int n_in,
                              void* d_out, int out_size) {
    const float *x = nullptr, *W0 = nullptr, *b0 = nullptr, *W1 = nullptr;
    const float *b1 = nullptr, *W2 = nullptr, *b2 = nullptr;
    for (int idx = 0; idx < n_in; ++idx) {
        switch (in_sizes[idx]) {
            case 131072:  x  = (const float*)d_in[idx]; break;   // [8192,16]
            case 65536:   W0 = (const float*)d_in[idx]; break;   // [4096,16]
            case 4096:    b0 = (const float*)d_in[idx]; break;
            case 8388608: W1 = (const float*)d_in[idx]; break;   // [2048,4096]
            case 2048:    b1 = (const float*)d_in[idx]; break;
            case 32768:   W2 = (const float*)d_in[idx]; break;   // [16,2048]
            case 16:      b2 = (const float*)d_in[idx]; break;
            default: break;
        }
    }

    const int n = out_size / 16;

    // gather/dup weights + preset out = b2  (needs >= 131072 threads)
    gather_kernel<<<512, 256>>>(W0, b0, W1, b1, W2, b2, (float*)d_out, out_size);

    const int chunks = (n + 255) / 256;
    mlp_kernel<<<chunks * 8, 256>>>(x, (float*)d_out, n);
}